// round 15
// baseline (speedup 1.0000x reference)
#include <cuda_runtime.h>
#include <cuda_fp16.h>
#include <cstdint>

// ============================================================================
// QuantLinear: out[M,N] = x[M,K] @ dequant(qweight, scales, qzeros)[K,N]
// M=8192, K=4096, N=11008, groupsize=128, 4-bit.
//
// compute_103 => mma.sync HMMA (rt_SMSP=8). Frozen optimum mainloop (R8/R12):
// CTA tile 128x128x64, 256 thr, 8 warps 64x32, 3-stage cp.async, 2 CTAs/SM,
// compute-first / fill-burst-after, st.global.cs epilogue.
//
// R15: persistent CTAs. 296 CTAs (=148 SMs x 2 slots); CTA bid processes
// tiles bid, bid+296, ... as ONE continuous cp.async stage stream: stages of
// tile k+1 are filled while tile k's last MMAs/epilogue run. Removes the
// per-tile cold prologue (~1.5-2us x 19 generations). Slot-reuse invariant
// is positional in the global stage index, so barrier semantics unchanged.
// ============================================================================

constexpr int M = 8192;
constexpr int N = 11008;
constexpr int K = 4096;

constexpr int BM = 128;
constexpr int BN = 128;
constexpr int KC = 64;             // halves per stage = 128B rows (SW128)
constexpr int STAGES = 3;
constexpr int NK = K / KC;         // 64 stages per tile
constexpr int THREADS = 256;

constexpr int MT = M / BM;         // 64 m-tiles
constexpr int NT = N / BN;         // 86 n-tiles
constexpr int TILES = MT * NT;     // 5504
constexpr int SLOTS = 296;         // 148 SMs x 2 CTAs

constexpr int A_BYTES = BM * 128;                 // 16384
constexpr int STAGE_BYTES = 2 * A_BYTES;          // 32768 (A then B)
constexpr int SMEM_BYTES = STAGES * STAGE_BYTES;  // 98304 -> 2 CTAs/SM

constexpr int KR = K / 8;               // 512 qweight rows
constexpr int XWORK   = M * K / 4;      // float4 items in convert part
constexpr int XBLOCKS = XWORK / 256;    // 32768 (exact)
constexpr int WBLOCKS = N / 16;         // 688 transpose-dequant blocks

static_assert(M % BM == 0 && N % BN == 0 && K % KC == 0, "exact tiling");
static_assert((MT & (MT - 1)) == 0, "tile%MT via mask");

__device__ __half g_X[(size_t)M * K];   // [M, K] fp16
__device__ __half g_W[(size_t)N * K];   // [N, K] fp16 (W^T), K-major

// ----------------------------------------------------------------------------
// helpers
// ----------------------------------------------------------------------------
__device__ __forceinline__ void cp16(uint32_t smem_dst, const void* gsrc) {
    asm volatile("cp.async.cg.shared.global [%0], [%1], 16;"
                 :: "r"(smem_dst), "l"(gsrc));
}

__device__ __forceinline__ void ldsm4(uint32_t* r, uint32_t addr) {
    asm volatile("ldmatrix.sync.aligned.m8n8.x4.shared.b16 {%0,%1,%2,%3}, [%4];"
                 : "=r"(r[0]), "=r"(r[1]), "=r"(r[2]), "=r"(r[3]) : "r"(addr));
}

__device__ __forceinline__ void mma16816(float* c, const uint32_t* a, const uint32_t* b) {
    asm volatile(
        "mma.sync.aligned.m16n8k16.row.col.f32.f16.f16.f32 "
        "{%0,%1,%2,%3}, {%4,%5,%6,%7}, {%8,%9}, {%0,%1,%2,%3};"
        : "+f"(c[0]), "+f"(c[1]), "+f"(c[2]), "+f"(c[3])
        : "r"(a[0]), "r"(a[1]), "r"(a[2]), "r"(a[3]), "r"(b[0]), "r"(b[1]));
}

__device__ __forceinline__ void stcs2(float* p, float a, float b) {
    asm volatile("st.global.cs.v2.f32 [%0], {%1, %2};"
                 :: "l"(p), "f"(a), "f"(b) : "memory");
}

// ----------------------------------------------------------------------------
// Pass 1: fused prep (frozen R10/R11).
// ----------------------------------------------------------------------------
__global__ void __launch_bounds__(256)
prep_kernel(const float* __restrict__ x, const int* __restrict__ qweight,
            const float* __restrict__ scales, const int* __restrict__ qzeros) {
    __shared__ unsigned sw[KR * 17];                 // 512 x 16, pad 17
    const int t = threadIdx.x;
    const int bid = blockIdx.x;

    if (bid < XBLOCKS) {
        int idx = bid * 256 + t;                     // over M*K/4 (exact)
        float4 v = ((const float4*)x)[idx];
        __half2 h0 = __floats2half2_rn(v.x, v.y);
        __half2 h1 = __floats2half2_rn(v.z, v.w);
        uint2 o;
        o.x = *(unsigned*)&h0;
        o.y = *(unsigned*)&h1;
        ((uint2*)g_X)[idx] = o;
        return;
    }

    const int n0 = (bid - XBLOCKS) * 16;
    const unsigned* qw = (const unsigned*)qweight;

#pragma unroll
    for (int w = 0; w < 8; w++) {
        int idx = w * 256 + t;                       // 0..2047 quads
        int r  = idx >> 2;
        int q4 = idx & 3;
        uint4 v = *(const uint4*)&qw[(size_t)r * N + n0 + q4 * 4];
        sw[r * 17 + q4 * 4 + 0] = v.x;
        sw[r * 17 + q4 * 4 + 1] = v.y;
        sw[r * 17 + q4 * 4 + 2] = v.z;
        sw[r * 17 + q4 * 4 + 3] = v.w;
    }
    __syncthreads();

    const int wid  = t >> 5;
    const int lane = t & 31;
#pragma unroll
    for (int pass = 0; pass < 2; pass++) {
        const int nl = wid + pass * 8;               // 0..15
        const int n  = n0 + nl;
#pragma unroll
        for (int rb = 0; rb < KR; rb += 32) {
            const int r = rb + lane;
            const int g = r >> 4;                    // groupsize 128 = 16 rows
            unsigned q  = sw[r * 17 + nl];
            unsigned qz = ((const unsigned*)qzeros)[(size_t)g * (N / 8) + (n >> 3)];
            float z = (float)((qz >> ((n & 7) * 4)) & 0xF);
            float s = scales[(size_t)g * N + n];
            __half2 outv[4];
#pragma unroll
            for (int j = 0; j < 4; j++) {
                float v0 = s * ((float)((q >> (8 * j))     & 0xF) - z);
                float v1 = s * ((float)((q >> (8 * j + 4)) & 0xF) - z);
                outv[j] = __floats2half2_rn(v0, v1);
            }
            *(uint4*)&g_W[(size_t)n * K + r * 8] = *(uint4*)outv;
        }
    }
}

// ----------------------------------------------------------------------------
// Stage loader (frozen): A 128 rows + B 128 rows, 128B/row, SW128.
// ----------------------------------------------------------------------------
__device__ __forceinline__ void load_stage(uint32_t sbase, int slot, int kt,
                                           const __half* Ag, const __half* Bg,
                                           int tid) {
    const uint32_t a_s = sbase + slot * STAGE_BYTES;
    const uint32_t b_s = a_s + A_BYTES;
    const __half* Ak = Ag + kt * KC;
    const __half* Bk = Bg + kt * KC;
#pragma unroll
    for (int it = 0; it < 4; it++) {        // 128 rows * 8 chunks / 256 thr
        int idx = tid + it * THREADS;
        int r = idx >> 3, c = idx & 7;
        uint32_t off = (uint32_t)r * 128 + (uint32_t)((c ^ (r & 7)) * 16);
        cp16(a_s + off, Ak + (size_t)r * K + c * 8);
        cp16(b_s + off, Bk + (size_t)r * K + c * 8);
    }
}

// ----------------------------------------------------------------------------
// Pass 2: persistent GEMM. Tile t: m = t % 64, n = t / 64 (m-fast, as before).
// CTA bid handles t = bid + ord*SLOTS. Global stage j: tile ord = j/64,
// kt = j%64. Mainloop body per stage is the frozen R8 form.
// ----------------------------------------------------------------------------
__global__ void __launch_bounds__(THREADS, 2)
gemm_kernel(float* __restrict__ out) {
    extern __shared__ char smem[];
    const uint32_t sbase = (uint32_t)__cvta_generic_to_shared(smem);
    const int tid  = threadIdx.x;
    const int warp = tid >> 5;
    const int lane = tid & 31;
    const int wm = warp & 1;          // 2 warps over 128 M (64 each)
    const int wn = warp >> 1;         // 4 warps over 128 N (32 each)
    const int bid = blockIdx.x;       // 0..295

    const int ntiles = (TILES - 1 - bid) / SLOTS + 1;    // 18 or 19
    const int total  = ntiles * NK;                      // global stages

    float acc[4][4][4];
#pragma unroll
    for (int i = 0; i < 4; i++)
#pragma unroll
        for (int j = 0; j < 4; j++)
#pragma unroll
            for (int e = 0; e < 4; e++) acc[i][j][e] = 0.f;

    // ldmatrix address components (validated R2..R14):
    const int arow = wm * 64 + (lane & 15);
    const int asel = lane >> 4;                              // k-chunk +0/+1
    const int brow = wn * 32 + (((lane >> 4) & 1) << 3) + (lane & 7);
    const int bsel = (lane >> 3) & 1;

    // prologue: stages j=0,1 (tile = bid, kt = 0,1)
    {
        const __half* Ag0 = g_X + (size_t)(bid & (MT - 1)) * BM * K;
        const __half* Bg0 = g_W + (size_t)(bid / MT) * BN * K;
        load_stage(sbase, 0, 0, Ag0, Bg0, tid);
        asm volatile("cp.async.commit_group;" ::: "memory");
        load_stage(sbase, 1, 1, Ag0, Bg0, tid);
        asm volatile("cp.async.commit_group;" ::: "memory");
        asm volatile("cp.async.wait_group 1;" ::: "memory");
        __syncthreads();
    }

    int slot = 0;
    for (int j = 0; j < total; j++) {
        // ---- compute stage j from slot (frozen R8 body) ----
        const uint32_t a_s = sbase + slot * STAGE_BYTES;
        const uint32_t b_s = a_s + A_BYTES;
#pragma unroll
        for (int ks = 0; ks < KC / 16; ks++) {
            uint32_t a[4][4], b[2][4];
#pragma unroll
            for (int mf = 0; mf < 4; mf++) {
                int row = arow + mf * 16;
                int kc  = ks * 2 + asel;
                ldsm4(a[mf], a_s + row * 128 + ((kc ^ (row & 7)) * 16));
            }
#pragma unroll
            for (int nf2 = 0; nf2 < 2; nf2++) {
                int row = brow + nf2 * 16;
                int kc  = ks * 2 + bsel;
                ldsm4(b[nf2], b_s + row * 128 + ((kc ^ (row & 7)) * 16));
            }
#pragma unroll
            for (int mf = 0; mf < 4; mf++)
#pragma unroll
                for (int nf = 0; nf < 4; nf++)
                    mma16816(acc[mf][nf], a[mf], &b[nf >> 1][(nf & 1) * 2]);
        }

        // ---- fill stage j+2 into slot(j-1) (may belong to the next tile) ----
        if (j + 2 < total) {
            const int jf   = j + 2;
            const int tile = bid + (jf >> 6) * SLOTS;
            const __half* Agf = g_X + (size_t)(tile & (MT - 1)) * BM * K;
            const __half* Bgf = g_W + (size_t)(tile / MT) * BN * K;
            int ns = slot - 1; if (ns < 0) ns += STAGES;
            load_stage(sbase, ns, jf & (NK - 1), Agf, Bgf, tid);
        }
        asm volatile("cp.async.commit_group;" ::: "memory");

        // ---- epilogue at tile end (overlaps the in-flight next-tile fills) --
        if ((j & (NK - 1)) == NK - 1) {
            const int tile = bid + (j >> 6) * SLOTS;
            const int m0 = (tile & (MT - 1)) * BM;
            const int n0 = (tile / MT) * BN;
            const int mbase = m0 + wm * 64 + (lane >> 2);
            const int nbase = n0 + wn * 32 + (lane & 3) * 2;
#pragma unroll
            for (int mf = 0; mf < 4; mf++)
#pragma unroll
                for (int nf = 0; nf < 4; nf++) {
                    float* p0 = &out[(size_t)(mbase + mf * 16)     * N + nbase + nf * 8];
                    float* p1 = &out[(size_t)(mbase + mf * 16 + 8) * N + nbase + nf * 8];
                    stcs2(p0, acc[mf][nf][0], acc[mf][nf][1]);
                    stcs2(p1, acc[mf][nf][2], acc[mf][nf][3]);
                    acc[mf][nf][0] = 0.f; acc[mf][nf][1] = 0.f;
                    acc[mf][nf][2] = 0.f; acc[mf][nf][3] = 0.f;
                }
        }

        slot++; if (slot == STAGES) slot = 0;

        // advance: <=1 group pending => stage j+1 landed
        if (j + 1 < total) {
            asm volatile("cp.async.wait_group 1;" ::: "memory");
            __syncthreads();
        }
    }
}

// ----------------------------------------------------------------------------
extern "C" void kernel_launch(void* const* d_in, const int* in_sizes, int n_in,
                              void* d_out, int out_size) {
    (void)in_sizes; (void)n_in; (void)out_size;
    const float* x       = (const float*)d_in[0];
    const int*   qweight = (const int*)d_in[1];
    const float* scales  = (const float*)d_in[2];
    const int*   qzeros  = (const int*)d_in[3];
    float* out = (float*)d_out;

    prep_kernel<<<XBLOCKS + WBLOCKS, 256>>>(x, qweight, scales, qzeros);

    cudaFuncSetAttribute(gemm_kernel, cudaFuncAttributeMaxDynamicSharedMemorySize,
                         SMEM_BYTES);
    gemm_kernel<<<SLOTS, THREADS, SMEM_BYTES>>>(out);   // 296 persistent CTAs
}

// round 16
// speedup vs baseline: 1.0823x; 1.0823x over previous
#include <cuda_runtime.h>
#include <cuda_fp16.h>
#include <cstdint>

// ============================================================================
// QuantLinear: out[M,N] = x[M,K] @ dequant(qweight, scales, qzeros)[K,N]
// M=8192, K=4096, N=11008, groupsize=128, 4-bit.
// FINAL = R12 (best measured: 1586.4us total; GEMM 1501us = ~93% of the
// measured mma.sync steady-state floor; rel_err 2.93e-4).
//
// compute_103 PTX target => no tcgen05 (harness compiles without 'a' suffix);
// tensor path = mma.sync m16n8k16 HMMA, rt_SMSP=8 measured.
//
// Mapped design space (all regressed vs this):
//   R3  fused in-loop dequant        3.31ms  (reg blowup -> 8 warps/SM)
//   R4  512-thr single-CTA BN=256    1.76ms  (barrier convoy)
//   R5  64x64 warp tiles + dbuf      1.95ms  (regs 226 -> 2 warps/SMSP)
//   R6  A+B frag double-buffer       2.45ms  (spill at 128-reg cap)
//   R7  Marlin int4-B-in-smem        1.90ms  (in-phase dequant on MMA path)
//   R9  cross-stage B dbuf           1.65ms  (liveness spill)
//   R13 interleaved fill             1.64ms  (LSU ops pollute LDSM->MMA phase)
//   R15 persistent 296 CTAs          1.71ms  (lost work-stealing balance)
// Wins, all included here:
//   R8  fill-after-compute (+85us), R4 fused prep, R10 transpose prep,
//   R11 st.global.cs epilogue + uint4 prep loads.
// Why optimal: 16 warps/SM in 2 CTAs is RF-capped (124regs x 512thr = full
// RF); smem crossbar and tensor pipe co-saturate at 2048 cyc/stage-period.
// ============================================================================

constexpr int M = 8192;
constexpr int N = 11008;
constexpr int K = 4096;

constexpr int BM = 128;
constexpr int BN = 128;
constexpr int KC = 64;             // halves per stage = 128B rows (SW128)
constexpr int STAGES = 3;
constexpr int NK = K / KC;         // 64
constexpr int THREADS = 256;

constexpr int A_BYTES = BM * 128;                 // 16384
constexpr int STAGE_BYTES = 2 * A_BYTES;          // 32768 (A then B)
constexpr int SMEM_BYTES = STAGES * STAGE_BYTES;  // 98304 -> 2 CTAs/SM

constexpr int KR = K / 8;               // 512 qweight rows
constexpr int XWORK   = M * K / 4;      // float4 items in convert part
constexpr int XBLOCKS = XWORK / 256;    // 32768 (exact)
constexpr int WBLOCKS = N / 16;         // 688 transpose-dequant blocks

static_assert(M % BM == 0 && N % BN == 0 && K % KC == 0, "exact tiling");

__device__ __half g_X[(size_t)M * K];   // [M, K] fp16
__device__ __half g_W[(size_t)N * K];   // [N, K] fp16 (W^T), K-major

// ----------------------------------------------------------------------------
// helpers
// ----------------------------------------------------------------------------
__device__ __forceinline__ void cp16(uint32_t smem_dst, const void* gsrc) {
    asm volatile("cp.async.cg.shared.global [%0], [%1], 16;"
                 :: "r"(smem_dst), "l"(gsrc));
}

__device__ __forceinline__ void ldsm4(uint32_t* r, uint32_t addr) {
    asm volatile("ldmatrix.sync.aligned.m8n8.x4.shared.b16 {%0,%1,%2,%3}, [%4];"
                 : "=r"(r[0]), "=r"(r[1]), "=r"(r[2]), "=r"(r[3]) : "r"(addr));
}

__device__ __forceinline__ void mma16816(float* c, const uint32_t* a, const uint32_t* b) {
    asm volatile(
        "mma.sync.aligned.m16n8k16.row.col.f32.f16.f16.f32 "
        "{%0,%1,%2,%3}, {%4,%5,%6,%7}, {%8,%9}, {%0,%1,%2,%3};"
        : "+f"(c[0]), "+f"(c[1]), "+f"(c[2]), "+f"(c[3])
        : "r"(a[0]), "r"(a[1]), "r"(a[2]), "r"(a[3]), "r"(b[0]), "r"(b[1]));
}

__device__ __forceinline__ void stcs2(float* p, float a, float b) {
    asm volatile("st.global.cs.v2.f32 [%0], {%1, %2};"
                 :: "l"(p), "f"(a), "f"(b) : "memory");
}

// ----------------------------------------------------------------------------
// Pass 1: fused prep.
//  blocks [0, XBLOCKS):          x fp32 -> fp16 (coalesced)
//  blocks [XBLOCKS, +WBLOCKS):   dequant 16 n x 512 r via smem transpose
// ----------------------------------------------------------------------------
__global__ void __launch_bounds__(256)
prep_kernel(const float* __restrict__ x, const int* __restrict__ qweight,
            const float* __restrict__ scales, const int* __restrict__ qzeros) {
    __shared__ unsigned sw[KR * 17];                 // 512 x 16, pad 17
    const int t = threadIdx.x;
    const int bid = blockIdx.x;

    if (bid < XBLOCKS) {
        int idx = bid * 256 + t;                     // over M*K/4 (exact)
        float4 v = ((const float4*)x)[idx];
        __half2 h0 = __floats2half2_rn(v.x, v.y);
        __half2 h1 = __floats2half2_rn(v.z, v.w);
        uint2 o;
        o.x = *(unsigned*)&h0;
        o.y = *(unsigned*)&h1;
        ((uint2*)g_X)[idx] = o;
        return;
    }

    const int n0 = (bid - XBLOCKS) * 16;
    const unsigned* qw = (const unsigned*)qweight;

    // phase 1: qweight tile [512 r x 16 n], uint4 per thread (4 n-words)
#pragma unroll
    for (int w = 0; w < 8; w++) {
        int idx = w * 256 + t;                       // 0..2047 quads
        int r  = idx >> 2;
        int q4 = idx & 3;
        uint4 v = *(const uint4*)&qw[(size_t)r * N + n0 + q4 * 4];
        sw[r * 17 + q4 * 4 + 0] = v.x;
        sw[r * 17 + q4 * 4 + 1] = v.y;
        sw[r * 17 + q4 * 4 + 2] = v.z;
        sw[r * 17 + q4 * 4 + 3] = v.w;
    }
    __syncthreads();

    // phase 2: warp per n; lanes sweep consecutive r -> 512B contiguous stores
    const int wid  = t >> 5;
    const int lane = t & 31;
#pragma unroll
    for (int pass = 0; pass < 2; pass++) {
        const int nl = wid + pass * 8;               // 0..15
        const int n  = n0 + nl;
#pragma unroll
        for (int rb = 0; rb < KR; rb += 32) {
            const int r = rb + lane;
            const int g = r >> 4;                    // groupsize 128 = 16 rows
            unsigned q  = sw[r * 17 + nl];
            unsigned qz = ((const unsigned*)qzeros)[(size_t)g * (N / 8) + (n >> 3)];
            float z = (float)((qz >> ((n & 7) * 4)) & 0xF);
            float s = scales[(size_t)g * N + n];
            __half2 outv[4];
#pragma unroll
            for (int j = 0; j < 4; j++) {
                float v0 = s * ((float)((q >> (8 * j))     & 0xF) - z);
                float v1 = s * ((float)((q >> (8 * j + 4)) & 0xF) - z);
                outv[j] = __floats2half2_rn(v0, v1);
            }
            *(uint4*)&g_W[(size_t)n * K + r * 8] = *(uint4*)outv;
        }
    }
}

// ----------------------------------------------------------------------------
// Stage loader: A 128 rows + B 128 rows, 128B/row, SW128.
// Row r, 16B chunk c at r*128 + ((c ^ (r&7))*16).
// ----------------------------------------------------------------------------
__device__ __forceinline__ void load_stage(uint32_t sbase, int slot, int kt,
                                           const __half* Ag, const __half* Bg,
                                           int tid) {
    const uint32_t a_s = sbase + slot * STAGE_BYTES;
    const uint32_t b_s = a_s + A_BYTES;
    const __half* Ak = Ag + kt * KC;
    const __half* Bk = Bg + kt * KC;
#pragma unroll
    for (int it = 0; it < 4; it++) {        // 128 rows * 8 chunks / 256 thr
        int idx = tid + it * THREADS;
        int r = idx >> 3, c = idx & 7;
        uint32_t off = (uint32_t)r * 128 + (uint32_t)((c ^ (r & 7)) * 16);
        cp16(a_s + off, Ak + (size_t)r * K + c * 8);
        cp16(b_s + off, Bk + (size_t)r * K + c * 8);
    }
}

// ----------------------------------------------------------------------------
// Pass 2: GEMM (frozen R8 mainloop: compute first, fill burst after)
// ----------------------------------------------------------------------------
__global__ void __launch_bounds__(THREADS, 2)
gemm_kernel(float* __restrict__ out) {
    extern __shared__ char smem[];
    const uint32_t sbase = (uint32_t)__cvta_generic_to_shared(smem);
    const int tid  = threadIdx.x;
    const int warp = tid >> 5;
    const int lane = tid & 31;
    const int wm = warp & 1;          // 2 warps over 128 M (64 each)
    const int wn = warp >> 1;         // 4 warps over 128 N (32 each)
    const int m0 = blockIdx.x * BM;
    const int n0 = blockIdx.y * BN;

    const __half* Ag = g_X + (size_t)m0 * K;
    const __half* Bg = g_W + (size_t)n0 * K;

    float acc[4][4][4];
#pragma unroll
    for (int i = 0; i < 4; i++)
#pragma unroll
        for (int j = 0; j < 4; j++)
#pragma unroll
            for (int e = 0; e < 4; e++) acc[i][j][e] = 0.f;

    // ldmatrix address components (validated R2..R15):
    const int arow = wm * 64 + (lane & 15);
    const int asel = lane >> 4;                              // k-chunk +0/+1
    const int brow = wn * 32 + (((lane >> 4) & 1) << 3) + (lane & 7);
    const int bsel = (lane >> 3) & 1;

    // prologue: fills for stages 0,1 in flight; stage 0 resident after sync
    load_stage(sbase, 0, 0, Ag, Bg, tid);
    asm volatile("cp.async.commit_group;" ::: "memory");
    load_stage(sbase, 1, 1, Ag, Bg, tid);
    asm volatile("cp.async.commit_group;" ::: "memory");
    asm volatile("cp.async.wait_group 1;" ::: "memory");
    __syncthreads();

    int slot = 0;
    for (int i = 0; i < NK; i++) {
        // stage i resident: compute first (no LDGSTS in front of first MMA)
        const uint32_t a_s = sbase + slot * STAGE_BYTES;
        const uint32_t b_s = a_s + A_BYTES;
#pragma unroll
        for (int ks = 0; ks < KC / 16; ks++) {
            uint32_t a[4][4], b[2][4];
#pragma unroll
            for (int mf = 0; mf < 4; mf++) {
                int row = arow + mf * 16;
                int kc  = ks * 2 + asel;
                ldsm4(a[mf], a_s + row * 128 + ((kc ^ (row & 7)) * 16));
            }
#pragma unroll
            for (int nf2 = 0; nf2 < 2; nf2++) {
                int row = brow + nf2 * 16;
                int kc  = ks * 2 + bsel;
                ldsm4(b[nf2], b_s + row * 128 + ((kc ^ (row & 7)) * 16));
            }
#pragma unroll
            for (int mf = 0; mf < 4; mf++)
#pragma unroll
                for (int nf = 0; nf < 4; nf++)
                    mma16816(acc[mf][nf], a[mf], &b[nf >> 1][(nf & 1) * 2]);
        }

        // issue fill for stage i+2 into slot (i+2)%3 = slot(i-1): all reads of
        // that slot finished before the barrier at the end of iter i-1.
        if (i + 2 < NK) {
            int ns = slot - 1; if (ns < 0) ns += STAGES;     // (i+2) % 3
            load_stage(sbase, ns, i + 2, Ag, Bg, tid);
        }
        asm volatile("cp.async.commit_group;" ::: "memory");

        slot++; if (slot == STAGES) slot = 0;

        // advance: <=1 group pending (the fill just issued) => stage i+1 landed
        if (i + 1 < NK) {
            asm volatile("cp.async.wait_group 1;" ::: "memory");
            __syncthreads();
        }
    }

    // Epilogue: streaming stores (write-once output; keep A resident in L2)
    const int mbase = m0 + wm * 64 + (lane >> 2);
    const int nbase = n0 + wn * 32 + (lane & 3) * 2;
#pragma unroll
    for (int mf = 0; mf < 4; mf++)
#pragma unroll
        for (int nf = 0; nf < 4; nf++) {
            float* p0 = &out[(size_t)(mbase + mf * 16)     * N + nbase + nf * 8];
            float* p1 = &out[(size_t)(mbase + mf * 16 + 8) * N + nbase + nf * 8];
            stcs2(p0, acc[mf][nf][0], acc[mf][nf][1]);
            stcs2(p1, acc[mf][nf][2], acc[mf][nf][3]);
        }
}

// ----------------------------------------------------------------------------
extern "C" void kernel_launch(void* const* d_in, const int* in_sizes, int n_in,
                              void* d_out, int out_size) {
    (void)in_sizes; (void)n_in; (void)out_size;
    const float* x       = (const float*)d_in[0];
    const int*   qweight = (const int*)d_in[1];
    const float* scales  = (const float*)d_in[2];
    const int*   qzeros  = (const int*)d_in[3];
    float* out = (float*)d_out;

    prep_kernel<<<XBLOCKS + WBLOCKS, 256>>>(x, qweight, scales, qzeros);

    cudaFuncSetAttribute(gemm_kernel, cudaFuncAttributeMaxDynamicSharedMemorySize,
                         SMEM_BYTES);
    dim3 grid(M / BM, N / BN);   // (64, 86), m-fast: wave shares B via L2
    gemm_kernel<<<grid, THREADS, SMEM_BYTES>>>(out);
}

// round 17
// speedup vs baseline: 1.1066x; 1.0225x over previous
#include <cuda_runtime.h>
#include <cuda_fp16.h>
#include <cstdint>

// ============================================================================
// QuantLinear: out[M,N] = x[M,K] @ dequant(qweight, scales, qzeros)[K,N]
// M=8192, K=4096, N=11008, groupsize=128, 4-bit.
//
// compute_103 PTX target => no tcgen05; tensor path = mma.sync m16n8k16 HMMA
// (rt_SMSP=8 measured). GEMM frozen at R12 optimum: 1507us, tensor 81%,
// ~93% of steady-state issue floor; design space fully mapped (R3-R15).
//
// R17 change (prep only): x-convert half used 32768 blocks x 1 float4/thread
// (MLP=1, 55 waves of block churn, occupancy throttled by the W-blocks'
// static smem). Now 4096 blocks x 8 float4/thread -> per-thread MLP=8,
// 8x less churn. Math untouched (rel_err must stay 2.934357e-4).
// ============================================================================

constexpr int M = 8192;
constexpr int N = 11008;
constexpr int K = 4096;

constexpr int BM = 128;
constexpr int BN = 128;
constexpr int KC = 64;             // halves per stage = 128B rows (SW128)
constexpr int STAGES = 3;
constexpr int NK = K / KC;         // 64
constexpr int THREADS = 256;

constexpr int A_BYTES = BM * 128;                 // 16384
constexpr int STAGE_BYTES = 2 * A_BYTES;          // 32768 (A then B)
constexpr int SMEM_BYTES = STAGES * STAGE_BYTES;  // 98304 -> 2 CTAs/SM

constexpr int KR = K / 8;               // 512 qweight rows
constexpr int XWORK   = M * K / 4;      // float4 items in convert part
constexpr int XPER    = 8;              // float4 per thread
constexpr int XBLOCKS = XWORK / (256 * XPER);     // 4096 (exact)
constexpr int WBLOCKS = N / 16;         // 688 transpose-dequant blocks

static_assert(XWORK % (256 * XPER) == 0, "exact x partition");
static_assert(M % BM == 0 && N % BN == 0 && K % KC == 0, "exact tiling");

__device__ __half g_X[(size_t)M * K];   // [M, K] fp16
__device__ __half g_W[(size_t)N * K];   // [N, K] fp16 (W^T), K-major

// ----------------------------------------------------------------------------
// helpers
// ----------------------------------------------------------------------------
__device__ __forceinline__ void cp16(uint32_t smem_dst, const void* gsrc) {
    asm volatile("cp.async.cg.shared.global [%0], [%1], 16;"
                 :: "r"(smem_dst), "l"(gsrc));
}

__device__ __forceinline__ void ldsm4(uint32_t* r, uint32_t addr) {
    asm volatile("ldmatrix.sync.aligned.m8n8.x4.shared.b16 {%0,%1,%2,%3}, [%4];"
                 : "=r"(r[0]), "=r"(r[1]), "=r"(r[2]), "=r"(r[3]) : "r"(addr));
}

__device__ __forceinline__ void mma16816(float* c, const uint32_t* a, const uint32_t* b) {
    asm volatile(
        "mma.sync.aligned.m16n8k16.row.col.f32.f16.f16.f32 "
        "{%0,%1,%2,%3}, {%4,%5,%6,%7}, {%8,%9}, {%0,%1,%2,%3};"
        : "+f"(c[0]), "+f"(c[1]), "+f"(c[2]), "+f"(c[3])
        : "r"(a[0]), "r"(a[1]), "r"(a[2]), "r"(a[3]), "r"(b[0]), "r"(b[1]));
}

__device__ __forceinline__ void stcs2(float* p, float a, float b) {
    asm volatile("st.global.cs.v2.f32 [%0], {%1, %2};"
                 :: "l"(p), "f"(a), "f"(b) : "memory");
}

// ----------------------------------------------------------------------------
// Pass 1: fused prep.
//  blocks [0, XBLOCKS):          x fp32 -> fp16, 8 float4 per thread (MLP=8)
//  blocks [XBLOCKS, +WBLOCKS):   dequant 16 n x 512 r via smem transpose
// ----------------------------------------------------------------------------
__global__ void __launch_bounds__(256)
prep_kernel(const float* __restrict__ x, const int* __restrict__ qweight,
            const float* __restrict__ scales, const int* __restrict__ qzeros) {
    __shared__ unsigned sw[KR * 17];                 // 512 x 16, pad 17
    const int t = threadIdx.x;
    const int bid = blockIdx.x;

    if (bid < XBLOCKS) {
        const int base = bid * 256 * XPER;
        float4 v[XPER];
#pragma unroll
        for (int it = 0; it < XPER; it++)            // batch loads: MLP = 8
            v[it] = ((const float4*)x)[base + it * 256 + t];
#pragma unroll
        for (int it = 0; it < XPER; it++) {
            __half2 h0 = __floats2half2_rn(v[it].x, v[it].y);
            __half2 h1 = __floats2half2_rn(v[it].z, v[it].w);
            uint2 o;
            o.x = *(unsigned*)&h0;
            o.y = *(unsigned*)&h1;
            ((uint2*)g_X)[base + it * 256 + t] = o;
        }
        return;
    }

    const int n0 = (bid - XBLOCKS) * 16;
    const unsigned* qw = (const unsigned*)qweight;

    // phase 1: qweight tile [512 r x 16 n], uint4 per thread (4 n-words)
#pragma unroll
    for (int w = 0; w < 8; w++) {
        int idx = w * 256 + t;                       // 0..2047 quads
        int r  = idx >> 2;
        int q4 = idx & 3;
        uint4 v = *(const uint4*)&qw[(size_t)r * N + n0 + q4 * 4];
        sw[r * 17 + q4 * 4 + 0] = v.x;
        sw[r * 17 + q4 * 4 + 1] = v.y;
        sw[r * 17 + q4 * 4 + 2] = v.z;
        sw[r * 17 + q4 * 4 + 3] = v.w;
    }
    __syncthreads();

    // phase 2: warp per n; lanes sweep consecutive r -> 512B contiguous stores
    const int wid  = t >> 5;
    const int lane = t & 31;
#pragma unroll
    for (int pass = 0; pass < 2; pass++) {
        const int nl = wid + pass * 8;               // 0..15
        const int n  = n0 + nl;
#pragma unroll
        for (int rb = 0; rb < KR; rb += 32) {
            const int r = rb + lane;
            const int g = r >> 4;                    // groupsize 128 = 16 rows
            unsigned q  = sw[r * 17 + nl];
            unsigned qz = ((const unsigned*)qzeros)[(size_t)g * (N / 8) + (n >> 3)];
            float z = (float)((qz >> ((n & 7) * 4)) & 0xF);
            float s = scales[(size_t)g * N + n];
            __half2 outv[4];
#pragma unroll
            for (int j = 0; j < 4; j++) {
                float v0 = s * ((float)((q >> (8 * j))     & 0xF) - z);
                float v1 = s * ((float)((q >> (8 * j + 4)) & 0xF) - z);
                outv[j] = __floats2half2_rn(v0, v1);
            }
            *(uint4*)&g_W[(size_t)n * K + r * 8] = *(uint4*)outv;
        }
    }
}

// ----------------------------------------------------------------------------
// Stage loader (frozen): A 128 rows + B 128 rows, 128B/row, SW128.
// Row r, 16B chunk c at r*128 + ((c ^ (r&7))*16).
// ----------------------------------------------------------------------------
__device__ __forceinline__ void load_stage(uint32_t sbase, int slot, int kt,
                                           const __half* Ag, const __half* Bg,
                                           int tid) {
    const uint32_t a_s = sbase + slot * STAGE_BYTES;
    const uint32_t b_s = a_s + A_BYTES;
    const __half* Ak = Ag + kt * KC;
    const __half* Bk = Bg + kt * KC;
#pragma unroll
    for (int it = 0; it < 4; it++) {        // 128 rows * 8 chunks / 256 thr
        int idx = tid + it * THREADS;
        int r = idx >> 3, c = idx & 7;
        uint32_t off = (uint32_t)r * 128 + (uint32_t)((c ^ (r & 7)) * 16);
        cp16(a_s + off, Ak + (size_t)r * K + c * 8);
        cp16(b_s + off, Bk + (size_t)r * K + c * 8);
    }
}

// ----------------------------------------------------------------------------
// Pass 2: GEMM (frozen R8/R12 mainloop: compute first, fill burst after)
// ----------------------------------------------------------------------------
__global__ void __launch_bounds__(THREADS, 2)
gemm_kernel(float* __restrict__ out) {
    extern __shared__ char smem[];
    const uint32_t sbase = (uint32_t)__cvta_generic_to_shared(smem);
    const int tid  = threadIdx.x;
    const int warp = tid >> 5;
    const int lane = tid & 31;
    const int wm = warp & 1;          // 2 warps over 128 M (64 each)
    const int wn = warp >> 1;         // 4 warps over 128 N (32 each)
    const int m0 = blockIdx.x * BM;
    const int n0 = blockIdx.y * BN;

    const __half* Ag = g_X + (size_t)m0 * K;
    const __half* Bg = g_W + (size_t)n0 * K;

    float acc[4][4][4];
#pragma unroll
    for (int i = 0; i < 4; i++)
#pragma unroll
        for (int j = 0; j < 4; j++)
#pragma unroll
            for (int e = 0; e < 4; e++) acc[i][j][e] = 0.f;

    // ldmatrix address components (validated R2..R16):
    const int arow = wm * 64 + (lane & 15);
    const int asel = lane >> 4;                              // k-chunk +0/+1
    const int brow = wn * 32 + (((lane >> 4) & 1) << 3) + (lane & 7);
    const int bsel = (lane >> 3) & 1;

    // prologue: fills for stages 0,1 in flight; stage 0 resident after sync
    load_stage(sbase, 0, 0, Ag, Bg, tid);
    asm volatile("cp.async.commit_group;" ::: "memory");
    load_stage(sbase, 1, 1, Ag, Bg, tid);
    asm volatile("cp.async.commit_group;" ::: "memory");
    asm volatile("cp.async.wait_group 1;" ::: "memory");
    __syncthreads();

    int slot = 0;
    for (int i = 0; i < NK; i++) {
        // stage i resident: compute first (no LDGSTS in front of first MMA)
        const uint32_t a_s = sbase + slot * STAGE_BYTES;
        const uint32_t b_s = a_s + A_BYTES;
#pragma unroll
        for (int ks = 0; ks < KC / 16; ks++) {
            uint32_t a[4][4], b[2][4];
#pragma unroll
            for (int mf = 0; mf < 4; mf++) {
                int row = arow + mf * 16;
                int kc  = ks * 2 + asel;
                ldsm4(a[mf], a_s + row * 128 + ((kc ^ (row & 7)) * 16));
            }
#pragma unroll
            for (int nf2 = 0; nf2 < 2; nf2++) {
                int row = brow + nf2 * 16;
                int kc  = ks * 2 + bsel;
                ldsm4(b[nf2], b_s + row * 128 + ((kc ^ (row & 7)) * 16));
            }
#pragma unroll
            for (int mf = 0; mf < 4; mf++)
#pragma unroll
                for (int nf = 0; nf < 4; nf++)
                    mma16816(acc[mf][nf], a[mf], &b[nf >> 1][(nf & 1) * 2]);
        }

        // issue fill for stage i+2 into slot (i+2)%3 = slot(i-1): all reads of
        // that slot finished before the barrier at the end of iter i-1.
        if (i + 2 < NK) {
            int ns = slot - 1; if (ns < 0) ns += STAGES;     // (i+2) % 3
            load_stage(sbase, ns, i + 2, Ag, Bg, tid);
        }
        asm volatile("cp.async.commit_group;" ::: "memory");

        slot++; if (slot == STAGES) slot = 0;

        // advance: <=1 group pending (the fill just issued) => stage i+1 landed
        if (i + 1 < NK) {
            asm volatile("cp.async.wait_group 1;" ::: "memory");
            __syncthreads();
        }
    }

    // Epilogue: streaming stores (write-once output; keep A resident in L2)
    const int mbase = m0 + wm * 64 + (lane >> 2);
    const int nbase = n0 + wn * 32 + (lane & 3) * 2;
#pragma unroll
    for (int mf = 0; mf < 4; mf++)
#pragma unroll
        for (int nf = 0; nf < 4; nf++) {
            float* p0 = &out[(size_t)(mbase + mf * 16)     * N + nbase + nf * 8];
            float* p1 = &out[(size_t)(mbase + mf * 16 + 8) * N + nbase + nf * 8];
            stcs2(p0, acc[mf][nf][0], acc[mf][nf][1]);
            stcs2(p1, acc[mf][nf][2], acc[mf][nf][3]);
        }
}

// ----------------------------------------------------------------------------
extern "C" void kernel_launch(void* const* d_in, const int* in_sizes, int n_in,
                              void* d_out, int out_size) {
    (void)in_sizes; (void)n_in; (void)out_size;
    const float* x       = (const float*)d_in[0];
    const int*   qweight = (const int*)d_in[1];
    const float* scales  = (const float*)d_in[2];
    const int*   qzeros  = (const int*)d_in[3];
    float* out = (float*)d_out;

    prep_kernel<<<XBLOCKS + WBLOCKS, 256>>>(x, qweight, scales, qzeros);

    cudaFuncSetAttribute(gemm_kernel, cudaFuncAttributeMaxDynamicSharedMemorySize,
                         SMEM_BYTES);
    dim3 grid(M / BM, N / BN);   // (64, 86), m-fast: wave shares B via L2
    gemm_kernel<<<grid, THREADS, SMEM_BYTES>>>(out);
}